// round 1
// baseline (speedup 1.0000x reference)
#include <cuda_runtime.h>

// Problem constants
#define BB   16
#define CIN  64
#define COUT 64
#define HH   128
#define WW   128
#define NKW  (COUT * CIN * 9)   // 36864
#define AWN  (NKW + COUT)       // 36928

// Conv tiling
#define TS    16   // spatial tile (16x16)
#define CICH  16   // ci chunk staged in smem
#define COG   16   // co per block
#define XPAD  19   // padded smem row stride (mild conflict reduction)

// Scratch (allocation-free rule: __device__ globals)
__device__ float g_h[BB * 30];
__device__ float g_aw[BB * AWN];

// ---------------------------------------------------------------------------
// MLP stage 1: h = relu(relu(z@W0^T + b0) @ W1^T + b1)   (per batch sample)
// ---------------------------------------------------------------------------
__global__ void mlp_h_kernel(const float* __restrict__ z,
                             const float* __restrict__ W0,
                             const float* __restrict__ b0,
                             const float* __restrict__ W1,
                             const float* __restrict__ b1) {
    const int b = blockIdx.x;
    const int t = threadIdx.x;
    __shared__ float h0[20];
    if (t < 20) {
        float s = b0[t];
        #pragma unroll
        for (int j = 0; j < 16; ++j) s += z[b * 16 + j] * W0[t * 16 + j];
        h0[t] = fmaxf(s, 0.0f);
    }
    __syncthreads();
    if (t < 30) {
        float s = b1[t];
        #pragma unroll
        for (int j = 0; j < 20; ++j) s += h0[j] * W1[t * 20 + j];
        g_h[b * 30 + t] = fmaxf(s, 0.0f);
    }
}

// ---------------------------------------------------------------------------
// MLP stage 2: aw[b, i] = relu(h[b] . W2[i] + b2[i])
// One thread owns one W2 row (read once), loops over all 16 batch h's.
// ---------------------------------------------------------------------------
__global__ __launch_bounds__(256) void mlp_aw_kernel(const float* __restrict__ W2,
                                                     const float* __restrict__ b2) {
    __shared__ float sh[BB * 30];
    const int tid = threadIdx.x;
    for (int j = tid; j < BB * 30; j += 256) sh[j] = g_h[j];
    __syncthreads();

    const int i = blockIdx.x * 256 + tid;
    if (i >= AWN) return;

    float w[30];
    #pragma unroll
    for (int j = 0; j < 30; ++j) w[j] = W2[i * 30 + j];
    const float bias = b2[i];

    #pragma unroll
    for (int b = 0; b < BB; ++b) {
        float s = bias;
        #pragma unroll
        for (int j = 0; j < 30; ++j) s += sh[b * 30 + j] * w[j];
        g_aw[b * AWN + i] = fmaxf(s, 0.0f);
    }
}

// ---------------------------------------------------------------------------
// Adaptive 3x3 SAME conv + bias + relu.
// Grid: (64 spatial tiles, 4 co-groups, 16 batch). Block: 256 threads.
// Per thread: 4 co x 4 horizontal pixels, ci chunked through smem.
// Inner loop per ci: 144 FFMA vs 54 LDS per warp -> FFMA-pipe bound.
// ---------------------------------------------------------------------------
__global__ __launch_bounds__(256) void conv_kernel(const float* __restrict__ x,
                                                   float* __restrict__ out) {
    __shared__ float sx[CICH][18][XPAD];     // 16 ci * 18x18 (+pad)
    __shared__ float sw[COG][CICH][9];       // 16 co * 16 ci * 9 taps

    const int tid  = threadIdx.x;
    const int tile = blockIdx.x;             // 0..63
    const int cog  = blockIdx.y;             // 0..3 (16 co each)
    const int b    = blockIdx.z;             // 0..15

    const int tx = (tile & 7) * TS;
    const int ty = (tile >> 3) * TS;

    // thread -> (row, 4-pixel quad, co sub-group)
    const int qid = tid & 63;
    const int row = qid >> 2;                // 0..15
    const int qx  = (qid & 3) * 4;           // 0,4,8,12
    const int cg  = tid >> 6;                // 0..3 -> co sub-group of 4

    float acc[4][4];
    #pragma unroll
    for (int a = 0; a < 4; ++a)
        #pragma unroll
        for (int p = 0; p < 4; ++p) acc[a][p] = 0.0f;

    const float* xb  = x + (size_t)b * CIN * HH * WW;
    const float* awb = g_aw + (size_t)b * AWN;

    for (int ch = 0; ch < CIN / CICH; ++ch) {
        __syncthreads();
        // Stage x chunk: 16 ci x 18x18 with SAME-padding zero fill
        for (int e = tid; e < CICH * 18 * 18; e += 256) {
            const int lci = e / (18 * 18);
            const int r   = (e / 18) % 18;
            const int c   = e % 18;
            const int gy  = ty + r - 1;
            const int gx  = tx + c - 1;
            float v = 0.0f;
            if (gy >= 0 && gy < HH && gx >= 0 && gx < WW)
                v = xb[((size_t)(ch * CICH + lci)) * HH * WW + gy * WW + gx];
            sx[lci][r][c] = v;
        }
        // Stage weights: 16 co x 16 ci x 9
        for (int e = tid; e < COG * CICH * 9; e += 256) {
            const int lco = e / (CICH * 9);
            const int rem = e % (CICH * 9);
            const int lci = rem / 9;
            const int t9  = rem % 9;
            sw[lco][lci][t9] =
                awb[((size_t)(cog * COG + lco) * CIN + ch * CICH + lci) * 9 + t9];
        }
        __syncthreads();

        #pragma unroll 1
        for (int lci = 0; lci < CICH; ++lci) {
            #pragma unroll
            for (int kh = 0; kh < 3; ++kh) {
                float xr[6];
                #pragma unroll
                for (int i = 0; i < 6; ++i) xr[i] = sx[lci][row + kh][qx + i];
                #pragma unroll
                for (int lco = 0; lco < 4; ++lco) {
                    const float w0 = sw[cg * 4 + lco][lci][kh * 3 + 0];
                    const float w1 = sw[cg * 4 + lco][lci][kh * 3 + 1];
                    const float w2 = sw[cg * 4 + lco][lci][kh * 3 + 2];
                    #pragma unroll
                    for (int p = 0; p < 4; ++p) {
                        acc[lco][p] = fmaf(xr[p + 0], w0, acc[lco][p]);
                        acc[lco][p] = fmaf(xr[p + 1], w1, acc[lco][p]);
                        acc[lco][p] = fmaf(xr[p + 2], w2, acc[lco][p]);
                    }
                }
            }
        }
    }

    // Epilogue: + per-(b,co) bias, relu, vectorized store
    #pragma unroll
    for (int lco = 0; lco < 4; ++lco) {
        const int co = cog * COG + cg * 4 + lco;
        const float bias = awb[NKW + co];
        float4 v;
        v.x = fmaxf(acc[lco][0] + bias, 0.0f);
        v.y = fmaxf(acc[lco][1] + bias, 0.0f);
        v.z = fmaxf(acc[lco][2] + bias, 0.0f);
        v.w = fmaxf(acc[lco][3] + bias, 0.0f);
        float* dst = out + (((size_t)b * COUT + co) * HH + (ty + row)) * WW + (tx + qx);
        *reinterpret_cast<float4*>(dst) = v;
    }
}

// ---------------------------------------------------------------------------
// Launch: MLP -> aw -> conv, all on the capture stream (default-stream launches)
// ---------------------------------------------------------------------------
extern "C" void kernel_launch(void* const* d_in, const int* in_sizes, int n_in,
                              void* d_out, int out_size) {
    const float* x  = (const float*)d_in[0];
    const float* z  = (const float*)d_in[1];
    const float* W0 = (const float*)d_in[2];
    const float* b0 = (const float*)d_in[3];
    const float* W1 = (const float*)d_in[4];
    const float* b1 = (const float*)d_in[5];
    const float* W2 = (const float*)d_in[6];
    const float* b2 = (const float*)d_in[7];
    float* out = (float*)d_out;

    mlp_h_kernel<<<BB, 32>>>(z, W0, b0, W1, b1);
    mlp_aw_kernel<<<(AWN + 255) / 256, 256>>>(W2, b2);

    dim3 grid(64, 4, BB);
    conv_kernel<<<grid, 256>>>(x, out);
}